// round 2
// baseline (speedup 1.0000x reference)
#include <cuda_runtime.h>
#include <cuda_bf16.h>
#include <cstdint>

// ---------------- problem constants ----------------
#define B_SZ 16384
#define P_N  128
#define V_N  128
#define W_N  64
#define BN_EPS 1e-5

// ---------------- scratch (static device globals; no allocation) ----------------
__device__ float          g_p[P_N * B_SZ];          // p[pathway][batch], 8 MB
__device__ __nv_bfloat16  g_W1bf[P_N * W_N * V_N];  // bf16 W1, row-major [p][w][v], 2 MB
__device__ double         g_S1[P_N], g_S2[P_N];
__device__ float          g_a[P_N];
__device__ float          g_c;

__device__ __forceinline__ uint32_t smem_u32(const void* p) {
    uint32_t a;
    asm("{ .reg .u64 t; cvta.to.shared.u64 t, %1; cvt.u32.u64 %0, t; }" : "=r"(a) : "l"(p));
    return a;
}

// swizzled byte offset inside a [rows][128 bf16] tile (256 B per row):
// XOR bits[4:6] of the in-row byte offset with row bits[0:2] -> conflict-free ldmatrix
__device__ __forceinline__ int swz(int row, int byte_in_row) {
    return row * 256 + (byte_in_row ^ ((row & 7) << 4));
}

__device__ __forceinline__ void ldmatrix_x4(uint32_t& r0, uint32_t& r1, uint32_t& r2, uint32_t& r3,
                                            uint32_t addr) {
    asm volatile("ldmatrix.sync.aligned.m8n8.x4.shared.b16 {%0,%1,%2,%3}, [%4];"
                 : "=r"(r0), "=r"(r1), "=r"(r2), "=r"(r3) : "r"(addr));
}

__device__ __forceinline__ void mma_bf16(float& c0, float& c1, float& c2, float& c3,
                                         uint32_t a0, uint32_t a1, uint32_t a2, uint32_t a3,
                                         uint32_t b0, uint32_t b1) {
    asm volatile("mma.sync.aligned.m16n8k16.row.col.f32.bf16.bf16.f32 "
                 "{%0,%1,%2,%3}, {%4,%5,%6,%7}, {%8,%9}, {%0,%1,%2,%3};"
                 : "+f"(c0), "+f"(c1), "+f"(c2), "+f"(c3)
                 : "r"(a0), "r"(a1), "r"(a2), "r"(a3), "r"(b0), "r"(b1));
}

// ============ K0: convert W1 fp32 -> bf16 row-major ============
__global__ __launch_bounds__(256) void k0_w1bf(const float* __restrict__ W1) {
    int idx = blockIdx.x * 256 + threadIdx.x;      // < 262144, each handles 4 elems
    float4 v = *reinterpret_cast<const float4*>(W1 + (size_t)idx * 4);
    __nv_bfloat162 lo = __float22bfloat162_rn(make_float2(v.x, v.y));
    __nv_bfloat162 hi = __float22bfloat162_rn(make_float2(v.z, v.w));
    uint2 pack = make_uint2(*reinterpret_cast<uint32_t*>(&lo), *reinterpret_cast<uint32_t*>(&hi));
    *reinterpret_cast<uint2*>(g_W1bf + (size_t)idx * 4) = pack;
}

// ============ K1: per-pathway [128x64x128] bf16 mma.sync + fused leaky/W2/leaky ============
// grid (B/128, P), 256 threads (8 warps). Warp w: rows m0 = 16*w.
__global__ __launch_bounds__(256) void k1_mma(const float* __restrict__ x,
                                              const float* __restrict__ W2) {
    extern __shared__ char smem[];                 // [0,32768) xs swizzled, [32768,49152) ws swizzled
    const uint32_t sb = smem_u32(smem);
    const int tid = threadIdx.x;
    const int wid = tid >> 5;
    const int lid = tid & 31;
    const int rb = blockIdx.x;                     // 128-row batch block
    const int p  = blockIdx.y;                     // pathway

    // ---- load + convert x tile: 128 rows x 128 fp32 -> bf16 swizzled smem ----
    {
        const float* xrow = x + (size_t)rb * 128 * (P_N * V_N) + (size_t)p * V_N;
        #pragma unroll
        for (int i = 0; i < 16; i++) {
            int idx = tid + i * 256;               // < 4096
            int r = idx >> 5;
            int c = (idx & 31);                    // float4 index in row
            float4 v = *reinterpret_cast<const float4*>(xrow + (size_t)r * (P_N * V_N) + c * 4);
            __nv_bfloat162 lo = __float22bfloat162_rn(make_float2(v.x, v.y));
            __nv_bfloat162 hi = __float22bfloat162_rn(make_float2(v.z, v.w));
            uint2 pack = make_uint2(*reinterpret_cast<uint32_t*>(&lo), *reinterpret_cast<uint32_t*>(&hi));
            *reinterpret_cast<uint2*>(smem + swz(r, c * 8)) = pack;
        }
    }
    // ---- copy W1 bf16 tile: 64 rows x 128 -> swizzled smem ----
    {
        const uint4* wsrc = reinterpret_cast<const uint4*>(g_W1bf + (size_t)p * (W_N * V_N));
        #pragma unroll
        for (int i = 0; i < 4; i++) {
            int idx = tid + i * 256;               // < 1024 16B-chunks
            int n = idx >> 4;
            int kc = idx & 15;
            *reinterpret_cast<uint4*>(smem + 32768 + swz(n, kc * 16)) = wsrc[idx];
        }
    }
    __syncthreads();

    // ---- mainloop: warp computes [16 x 64], K=128 ----
    float acc[8][4];
    #pragma unroll
    for (int t = 0; t < 8; t++)
        #pragma unroll
        for (int j = 0; j < 4; j++) acc[t][j] = 0.f;

    const int m0 = wid * 16;
    const uint32_t a_row = m0 + (lid & 15);
    const uint32_t a_chunk = (lid >> 4) * 16;
    const int bg = lid >> 3;                        // 0..3 address group
    const int b_nrow_off = (lid & 7) + ((bg >= 2) ? 8 : 0);
    const int b_koff = (bg & 1) * 16;

    #pragma unroll
    for (int ks = 0; ks < 8; ks++) {
        const int kb = ks * 32;                     // byte offset of k-step in row
        uint32_t a0, a1, a2, a3;
        ldmatrix_x4(a0, a1, a2, a3, sb + swz(a_row, kb + a_chunk));
        #pragma unroll
        for (int t = 0; t < 4; t++) {
            uint32_t b0, b1, b2, b3;
            ldmatrix_x4(b0, b1, b2, b3,
                        sb + 32768 + swz(t * 16 + b_nrow_off, kb + b_koff));
            mma_bf16(acc[2*t][0], acc[2*t][1], acc[2*t][2], acc[2*t][3],
                     a0, a1, a2, a3, b0, b1);
            mma_bf16(acc[2*t+1][0], acc[2*t+1][1], acc[2*t+1][2], acc[2*t+1][3],
                     a0, a1, a2, a3, b2, b3);
        }
    }

    // ---- epilogue: h=leaky(acc); dot with W2 over n; p=leaky(dot) ----
    {
        const float2* w2p = reinterpret_cast<const float2*>(W2 + (size_t)p * W_N);
        float sum0 = 0.f, sum1 = 0.f;               // rows (lid>>2), (lid>>2)+8
        #pragma unroll
        for (int t = 0; t < 8; t++) {
            float2 w2v = __ldg(&w2p[t * 4 + (lid & 3)]);   // cols t*8 + (lid&3)*2, +1
            float h;
            h = acc[t][0]; h = (h >= 0.f) ? h : 0.2f * h; sum0 += h * w2v.x;
            h = acc[t][1]; h = (h >= 0.f) ? h : 0.2f * h; sum0 += h * w2v.y;
            h = acc[t][2]; h = (h >= 0.f) ? h : 0.2f * h; sum1 += h * w2v.x;
            h = acc[t][3]; h = (h >= 0.f) ? h : 0.2f * h; sum1 += h * w2v.y;
        }
        // reduce across the 4 lanes of each quad (they share the same rows)
        sum0 += __shfl_xor_sync(0xFFFFFFFF, sum0, 1);
        sum0 += __shfl_xor_sync(0xFFFFFFFF, sum0, 2);
        sum1 += __shfl_xor_sync(0xFFFFFFFF, sum1, 1);
        sum1 += __shfl_xor_sync(0xFFFFFFFF, sum1, 2);
        if ((lid & 3) == 0) {
            int row = lid >> 2;
            float pv0 = (sum0 >= 0.f) ? sum0 : 0.2f * sum0;
            float pv1 = (sum1 >= 0.f) ? sum1 : 0.2f * sum1;
            float* dst = g_p + (size_t)p * B_SZ + rb * 128 + m0;
            dst[row] = pv0;
            dst[row + 8] = pv1;
        }
    }
}

// ============ K2a: per-pathway sum / sumsq (fp64) ============
__global__ __launch_bounds__(256) void k2a_reduce() {
    const int p = blockIdx.x;
    const int tid = threadIdx.x;
    const float* col = g_p + (size_t)p * B_SZ;
    double a1 = 0.0, a2 = 0.0;
    for (int i = tid; i < B_SZ; i += 256) {
        double v = (double)col[i];
        a1 += v;
        a2 += v * v;
    }
    __shared__ double s1[256], s2[256];
    s1[tid] = a1; s2[tid] = a2;
    __syncthreads();
    for (int o = 128; o > 0; o >>= 1) {
        if (tid < o) { s1[tid] += s1[tid + o]; s2[tid] += s2[tid + o]; }
        __syncthreads();
    }
    if (tid == 0) { g_S1[p] = s1[0]; g_S2[p] = s2[0]; }
}

// ============ K2b: collapse BN + global-L2 + disease projection into a_p, c ============
__global__ __launch_bounds__(128) void k2b_finalize(
    const float* __restrict__ gamma, const float* __restrict__ beta,
    const float* __restrict__ Wd, const float* __restrict__ bdp) {
    const int p = threadIdx.x;
    const double Bd = (double)B_SZ;
    double mean = g_S1[p] / Bd;
    double var = g_S2[p] / Bd - mean * mean;
    if (var < 0.0) var = 0.0;
    double sig2 = var + (double)BN_EPS;
    double inv_sigma = 1.0 / sqrt(sig2);
    double g = (double)gamma[p], bt = (double)beta[p], wd = (double)Wd[p];
    double nsq = g * g * Bd * var / sig2 + Bd * bt * bt;   // sum over b of pn^2 for this p
    double t = (bt - mean * g * inv_sigma) * wd;

    __shared__ double sn[128], st[128];
    sn[p] = nsq; st[p] = t;
    __syncthreads();
    for (int o = 64; o > 0; o >>= 1) {
        if (p < o) { sn[p] += sn[p + o]; st[p] += st[p + o]; }
        __syncthreads();
    }
    __shared__ double norm_s, T_s;
    if (p == 0) { norm_s = sqrt(sn[0]); T_s = st[0]; }
    __syncthreads();
    double norm = norm_s;
    g_a[p] = (float)(g * wd * inv_sigma / norm);
    if (p == 0) g_c = (float)(T_s / norm + (double)bdp[0]);
}

// ============ K3: out[b] = sigmoid(sum_p p[b,p]*a_p + c) ============
__global__ __launch_bounds__(256) void k3_out(float* __restrict__ out) {
    __shared__ float sa[128];
    __shared__ float sc;
    const int tid = threadIdx.x;
    if (tid < 128) sa[tid] = g_a[tid];
    if (tid == 0) sc = g_c;
    __syncthreads();
    const int b = blockIdx.x * 256 + tid;
    float acc = 0.f;
    #pragma unroll 8
    for (int p = 0; p < P_N; p++) acc += g_p[(size_t)p * B_SZ + b] * sa[p];
    float z = acc + sc;
    out[b] = 1.f / (1.f + expf(-z));
}

// ============ launch ============
extern "C" void kernel_launch(void* const* d_in, const int* in_sizes, int n_in,
                              void* d_out, int out_size) {
    const float* x     = (const float*)d_in[0];
    const float* W1    = (const float*)d_in[1];
    const float* W2    = (const float*)d_in[2];
    const float* gamma = (const float*)d_in[3];
    const float* beta  = (const float*)d_in[4];
    const float* Wd    = (const float*)d_in[5];
    const float* bdp   = (const float*)d_in[6];
    float* out = (float*)d_out;

    k0_w1bf<<<1024, 256>>>(W1);
    k1_mma<<<dim3(B_SZ / 128, P_N), 256, 49152>>>(x, W2);
    k2a_reduce<<<P_N, 256>>>();
    k2b_finalize<<<1, 128>>>(gamma, beta, Wd, bdp);
    k3_out<<<B_SZ / 256, 256>>>(out);
}